// round 5
// baseline (speedup 1.0000x reference)
#include <cuda_runtime.h>
#include <cuda_bf16.h>
#include <cstdint>
#include <cstddef>

#define B_TOT 32768
#define D_IN  128
#define A_DIM 16
#define H1D   600
#define H2D   500
#define KP    640
#define G_N   8

#define CK     64
#define ROWB   144u
#define A_HALF 18432u                 // 128 rows * 144B
#define STAGE_BYTES (4u*A_HALF)       // Ah|Al|Bh|Bl = 73728
#define SMEM_BYTES  (2*STAGE_BYTES + 2048)

// ---- persistent device scratch (pre-split bf16 hi/lo operands) ----
__device__ __nv_bfloat16 g_h1hi[(size_t)B_TOT * KP];
__device__ __nv_bfloat16 g_h1lo[(size_t)B_TOT * KP];
__device__ __nv_bfloat16 g_Sh[(size_t)B_TOT * D_IN];
__device__ __nv_bfloat16 g_Sl[(size_t)B_TOT * D_IN];
__device__ __nv_bfloat16 g_W1h[(size_t)G_N * 640 * D_IN];
__device__ __nv_bfloat16 g_W1l[(size_t)G_N * 640 * D_IN];
__device__ __nv_bfloat16 g_W2h[(size_t)512 * 576];
__device__ __nv_bfloat16 g_W2l[(size_t)512 * 576];
__device__ __nv_bfloat16 g_Bth[(size_t)G_N * 512 * 64];
__device__ __nv_bfloat16 g_Btl[(size_t)G_N * 512 * 64];

// ---------------- helpers ----------------
__device__ __forceinline__ uint32_t smem_u32(const void* p) {
    uint32_t a;
    asm("{ .reg .u64 t; cvta.to.shared.u64 t, %1; cvt.u32.u64 %0, t; }" : "=r"(a) : "l"(p));
    return a;
}
__device__ __forceinline__ void ldm_x4(uint32_t* r, uint32_t addr) {
    asm volatile("ldmatrix.sync.aligned.m8n8.x4.shared.b16 {%0,%1,%2,%3}, [%4];"
                 : "=r"(r[0]), "=r"(r[1]), "=r"(r[2]), "=r"(r[3]) : "r"(addr));
}
__device__ __forceinline__ void mma16816(float* c, const uint32_t* a, const uint32_t* b) {
    asm volatile("mma.sync.aligned.m16n8k16.row.col.f32.bf16.bf16.f32 "
                 "{%0,%1,%2,%3}, {%4,%5,%6,%7}, {%8,%9}, {%0,%1,%2,%3};"
                 : "+f"(c[0]), "+f"(c[1]), "+f"(c[2]), "+f"(c[3])
                 : "r"(a[0]), "r"(a[1]), "r"(a[2]), "r"(a[3]), "r"(b[0]), "r"(b[1]));
}
__device__ __forceinline__ void cp16(uint32_t dst, const void* src) {
    asm volatile("cp.async.cg.shared.global [%0], [%1], 16;" :: "r"(dst), "l"(src) : "memory");
}
__device__ __forceinline__ void cp_commit() { asm volatile("cp.async.commit_group;" ::: "memory"); }
__device__ __forceinline__ void cp_wait0() { asm volatile("cp.async.wait_group 0;" ::: "memory"); }

__device__ __forceinline__ uint32_t pack2(float f0, float f1) {
    uint32_t r;
    asm("cvt.rn.bf16x2.f32 %0, %1, %2;" : "=r"(r) : "f"(f1), "f"(f0));
    return r;
}
__device__ __forceinline__ void split2(float f0, float f1, uint32_t& h, uint32_t& l) {
    h = pack2(f0, f1);
    float h0 = __uint_as_float(h << 16);
    float h1 = __uint_as_float(h & 0xffff0000u);
    l = pack2(f0 - h0, f1 - h1);
}
__device__ __forceinline__ void split8(float4 v0, float4 v1, uint4& H, uint4& L) {
    split2(v0.x, v0.y, H.x, L.x);
    split2(v0.z, v0.w, H.y, L.y);
    split2(v1.x, v1.y, H.z, L.z);
    split2(v1.z, v1.w, H.w, L.w);
}

// ---------------- fused prep kernel ----------------
// block regions: [0,128) init_out | [128,256) fill_pad | [256,2304) split_state
//                [2304,2624) split_W1 | [2624,2768) split_W2 | [2768,2896) split_Bt
#define PREP_BLOCKS 2896
__global__ __launch_bounds__(256) void prep_kernel(const float* __restrict__ state,
                                                   const float* __restrict__ action,
                                                   const int* __restrict__ idx,
                                                   const float* __restrict__ W1,
                                                   const float* __restrict__ W2s,
                                                   const float* __restrict__ W2a,
                                                   const float* __restrict__ b3,
                                                   float* __restrict__ out) {
    const int blk = blockIdx.x;
    const int t = threadIdx.x;
    if (blk < 128) {
        int i = blk * 256 + t;
        out[i] = b3[idx[i]];
    } else if (blk < 256) {
        int b = (blk - 128) * 256 + t;
        const float4* a4 = (const float4*)(action + (size_t)b * A_DIM);
        uint4 H0, L0, H1, L1;
        split8(a4[0], a4[1], H0, L0);
        split8(a4[2], a4[3], H1, L1);
        uint16_t* ph = (uint16_t*)g_h1hi + (size_t)b * KP + 600;
        uint16_t* pl = (uint16_t*)g_h1lo + (size_t)b * KP + 600;
        ((uint4*)ph)[0] = H0; ((uint4*)ph)[1] = H1;
        ((uint4*)pl)[0] = L0; ((uint4*)pl)[1] = L1;
        uint4 z = make_uint4(0, 0, 0, 0);
        ((uint4*)(ph + 16))[0] = z; ((uint4*)(ph + 16))[1] = z; ((uint4*)(ph + 16))[2] = z;
        ((uint4*)(pl + 16))[0] = z; ((uint4*)(pl + 16))[1] = z; ((uint4*)(pl + 16))[2] = z;
    } else if (blk < 2304) {
        size_t e = ((size_t)(blk - 256) * 256 + t) * 8;
        const float4* s4 = (const float4*)(state + e);
        uint4 H, L;
        split8(s4[0], s4[1], H, L);
        *(uint4*)((uint16_t*)g_Sh + e) = H;
        *(uint4*)((uint16_t*)g_Sl + e) = L;
    } else if (blk < 2624) {
        size_t e = ((size_t)(blk - 2304) * 256 + t) * 8;
        int g = (int)(e / (640 * D_IN));
        int r = (int)((e / D_IN) % 640);
        int c = (int)(e % D_IN);
        uint4 H = make_uint4(0, 0, 0, 0), L = H;
        if (r < H1D) {
            const float4* s4 = (const float4*)(W1 + ((size_t)g * H1D + r) * D_IN + c);
            split8(s4[0], s4[1], H, L);
        }
        *(uint4*)((uint16_t*)g_W1h + e) = H;
        *(uint4*)((uint16_t*)g_W1l + e) = L;
    } else if (blk < 2768) {
        size_t e = ((size_t)(blk - 2624) * 256 + t) * 8;
        int n = (int)(e / 576);
        int c = (int)(e % 576);
        uint4 H = make_uint4(0, 0, 0, 0), L = H;
        if (n < H2D) {
            const float4* s4 = (const float4*)(W2s + (size_t)n * H1D + c);
            split8(s4[0], s4[1], H, L);
        }
        *(uint4*)((uint16_t*)g_W2h + e) = H;
        *(uint4*)((uint16_t*)g_W2l + e) = L;
    } else {
        size_t e = ((size_t)(blk - 2768) * 256 + t) * 8;
        int g = (int)(e / (512 * 64));
        int n = (int)((e / 64) % 512);
        int cc = (int)(e % 64);
        float v[8];
        #pragma unroll
        for (int j = 0; j < 8; j++) {
            int c = cc + j;
            float x = 0.f;
            if (n < H2D) {
                if (c < 24) x = W2s[(size_t)n * H1D + 576 + c];
                else if (c < 40) x = W2a[((size_t)g * H2D + n) * A_DIM + (c - 24)];
            }
            v[j] = x;
        }
        uint4 H, L;
        split8(make_float4(v[0], v[1], v[2], v[3]), make_float4(v[4], v[5], v[6], v[7]), H, L);
        *(uint4*)((uint16_t*)g_Bth + e) = H;
        *(uint4*)((uint16_t*)g_Btl + e) = L;
    }
}

// ---------------- mma body: stage = [Ah|Al|Bh|Bl], each 128 rows x 144B ----------------
#define MMA_STAGE(sbase, s)                                                        \
    {                                                                              \
        const uint32_t SA = (sbase) + (uint32_t)(s) * STAGE_BYTES;                 \
        const uint32_t SAh = SA, SAl = SA + A_HALF;                                \
        const uint32_t SBh = SA + 2u * A_HALF, SBl = SA + 3u * A_HALF;             \
        _Pragma("unroll")                                                          \
        for (int kk = 0; kk < 4; kk++) {                                           \
            uint32_t ah[2][4], al[2][4], bh[4][2], bl[4][2];                       \
            _Pragma("unroll")                                                      \
            for (int mf = 0; mf < 2; mf++) {                                       \
                ldm_x4(ah[mf], SAh + aoff + mf * 2304u + kk * 32u);                \
                ldm_x4(al[mf], SAl + aoff + mf * 2304u + kk * 32u);                \
            }                                                                      \
            _Pragma("unroll")                                                      \
            for (int nq = 0; nq < 2; nq++) {                                       \
                uint32_t t[4];                                                     \
                ldm_x4(t, SBh + boff + nq * 2304u + kk * 32u);                     \
                bh[nq * 2][0] = t[0]; bh[nq * 2][1] = t[2];                        \
                bh[nq * 2 + 1][0] = t[1]; bh[nq * 2 + 1][1] = t[3];                \
                ldm_x4(t, SBl + boff + nq * 2304u + kk * 32u);                     \
                bl[nq * 2][0] = t[0]; bl[nq * 2][1] = t[2];                        \
                bl[nq * 2 + 1][0] = t[1]; bl[nq * 2 + 1][1] = t[3];                \
            }                                                                      \
            _Pragma("unroll")                                                      \
            for (int mf = 0; mf < 2; mf++)                                         \
                _Pragma("unroll")                                                  \
                for (int nf = 0; nf < 4; nf++) {                                   \
                    mma16816(C[mf][nf], ah[mf], bh[nf]);                           \
                    mma16816(C[mf][nf], ah[mf], bl[nf]);                           \
                    mma16816(C[mf][nf], al[mf], bh[nf]);                           \
                }                                                                  \
        }                                                                          \
    }

// GEMM1: h1 = relu(state . W1[g]^T + b1[g]) -> g_h1 hi/lo. M=128,N=128,K=128 (2 chunks)
__global__ __launch_bounds__(512, 1) void h1_mma_kernel(const int* __restrict__ idx,
                                                        const float* __restrict__ b1) {
    extern __shared__ char dsm[];
    const uint32_t sbase = smem_u32(dsm);
    float* sb1 = (float*)(dsm + 2 * STAGE_BYTES);
    int* sidx = (int*)(sb1 + 128);
    const int tid = threadIdx.x, lane = tid & 31, wid = tid >> 5;
    const int n0 = blockIdx.x * 128, b0 = blockIdx.y * 128;
    if (tid < 128) sidx[tid] = idx[b0 + tid];
    __syncthreads();
    const int g_lo = sidx[0], g_hi = sidx[127];
    const int m_base = (wid >> 2) * 32, n_base = (wid & 3) * 32;
    const uint32_t aoff = (uint32_t)(m_base + (lane & 15)) * ROWB + (uint32_t)((lane >> 4) * 16);
    const uint32_t boff = (uint32_t)(n_base + (lane & 15)) * ROWB + (uint32_t)((lane >> 4) * 16);

    for (int g = g_lo; g <= g_hi; ++g) {
        if (tid < 128) { int n = n0 + tid; sb1[tid] = (n < H1D) ? b1[(size_t)g * H1D + n] : 0.f; }
        auto issue = [&](int kc, int s) {
            #pragma unroll
            for (int i = 0; i < 4; i++) {
                int bid = tid + i * 512;
                int arr = bid >> 10, rem = bid & 1023;
                int row = rem >> 3, q = rem & 7;
                const __nv_bfloat16* src = (arr ? g_Sl : g_Sh) + (size_t)(b0 + row) * D_IN + kc * CK + q * 8;
                cp16(sbase + (uint32_t)s * STAGE_BYTES + (uint32_t)arr * A_HALF + row * ROWB + q * 16u, src);
            }
            #pragma unroll
            for (int i = 0; i < 4; i++) {
                int bid = tid + i * 512;
                int arr = bid >> 10, rem = bid & 1023;
                int row = rem >> 3, q = rem & 7;
                const __nv_bfloat16* src = (arr ? g_W1l : g_W1h) + ((size_t)g * 640 + n0 + row) * D_IN + kc * CK + q * 8;
                cp16(sbase + (uint32_t)s * STAGE_BYTES + (2u + (uint32_t)arr) * A_HALF + row * ROWB + q * 16u, src);
            }
            cp_commit();
        };
        float C[2][4][4];
        #pragma unroll
        for (int mf = 0; mf < 2; mf++)
            #pragma unroll
            for (int nf = 0; nf < 4; nf++)
                #pragma unroll
                for (int e = 0; e < 4; e++) C[mf][nf][e] = 0.f;

        issue(0, 0);
        cp_wait0();
        __syncthreads();
        issue(1, 1);
        MMA_STAGE(sbase, 0);
        cp_wait0();
        __syncthreads();
        MMA_STAGE(sbase, 1);

        // epilogue: +b1, relu, split, store rows owned by g
        #pragma unroll
        for (int mf = 0; mf < 2; mf++)
            #pragma unroll
            for (int half = 0; half < 2; half++) {
                int r = m_base + mf * 16 + (lane >> 2) + half * 8;
                if (sidx[r] == g) {
                    size_t base = (size_t)(b0 + r) * KP;
                    #pragma unroll
                    for (int nf = 0; nf < 4; nf++) {
                        int lc = n_base + nf * 8 + 2 * (lane & 3);
                        int n = n0 + lc;
                        if (n < H1D) {
                            float v0 = fmaxf(C[mf][nf][half * 2 + 0] + sb1[lc], 0.f);
                            float v1 = fmaxf(C[mf][nf][half * 2 + 1] + sb1[lc + 1], 0.f);
                            uint32_t h, l;
                            split2(v0, v1, h, l);
                            *(uint32_t*)(g_h1hi + base + n) = h;
                            *(uint32_t*)(g_h1lo + base + n) = l;
                        }
                    }
                }
            }
        __syncthreads();
    }
}

// GEMM2 fused: q += relu([h1|act|0].[W2s|W2a[g]|0]^T + b2s) . W3[g]. M=128,N=128,K=640
__global__ __launch_bounds__(512, 1) void h2q_mma_kernel(const int* __restrict__ idx,
                                                         const float* __restrict__ b2s,
                                                         const float* __restrict__ W3,
                                                         float* __restrict__ out) {
    extern __shared__ char dsm[];
    const uint32_t sbase = smem_u32(dsm);
    float* sb2 = (float*)(dsm + 2 * STAGE_BYTES);
    float* sw3 = sb2 + 128;
    int* sidx = (int*)(sw3 + 128);
    const int tid = threadIdx.x, lane = tid & 31, wid = tid >> 5;
    const int n0 = blockIdx.x * 128, b0 = blockIdx.y * 128;
    if (tid < 128) {
        sidx[tid] = idx[b0 + tid];
        int n = n0 + tid;
        sb2[tid] = (n < H2D) ? b2s[n] : 0.f;
    }
    __syncthreads();
    const int g_lo = sidx[0], g_hi = sidx[127];
    const int m_base = (wid >> 2) * 32, n_base = (wid & 3) * 32;
    const uint32_t aoff = (uint32_t)(m_base + (lane & 15)) * ROWB + (uint32_t)((lane >> 4) * 16);
    const uint32_t boff = (uint32_t)(n_base + (lane & 15)) * ROWB + (uint32_t)((lane >> 4) * 16);

    for (int g = g_lo; g <= g_hi; ++g) {
        if (tid < 128) { int n = n0 + tid; sw3[tid] = (n < H2D) ? W3[(size_t)g * H2D + n] : 0.f; }
        auto issue = [&](int kc, int s) {
            #pragma unroll
            for (int i = 0; i < 4; i++) {
                int bid = tid + i * 512;
                int arr = bid >> 10, rem = bid & 1023;
                int row = rem >> 3, q = rem & 7;
                const __nv_bfloat16* src = (arr ? g_h1lo : g_h1hi) + (size_t)(b0 + row) * KP + kc * CK + q * 8;
                cp16(sbase + (uint32_t)s * STAGE_BYTES + (uint32_t)arr * A_HALF + row * ROWB + q * 16u, src);
            }
            #pragma unroll
            for (int i = 0; i < 4; i++) {
                int bid = tid + i * 512;
                int arr = bid >> 10, rem = bid & 1023;
                int row = rem >> 3, q = rem & 7;
                const __nv_bfloat16* src;
                if (kc < 9)
                    src = (arr ? g_W2l : g_W2h) + (size_t)(n0 + row) * 576 + kc * CK + q * 8;
                else
                    src = (arr ? g_Btl : g_Bth) + ((size_t)g * 512 + n0 + row) * 64 + q * 8;
                cp16(sbase + (uint32_t)s * STAGE_BYTES + (2u + (uint32_t)arr) * A_HALF + row * ROWB + q * 16u, src);
            }
            cp_commit();
        };

        float C[2][4][4];
        #pragma unroll
        for (int mf = 0; mf < 2; mf++)
            #pragma unroll
            for (int nf = 0; nf < 4; nf++)
                #pragma unroll
                for (int e = 0; e < 4; e++) C[mf][nf][e] = 0.f;

        issue(0, 0);
        for (int kc = 0; kc < 10; ++kc) {
            cp_wait0();
            __syncthreads();                 // chunk kc ready; MMA(kc-1) finished by all warps
            if (kc < 9) issue(kc + 1, (kc + 1) & 1);
            MMA_STAGE(sbase, kc & 1);
        }

        // epilogue: relu(+b2s) . W3, quad-reduce, atomicAdd
        #pragma unroll
        for (int mf = 0; mf < 2; mf++)
            #pragma unroll
            for (int half = 0; half < 2; half++) {
                int r = m_base + mf * 16 + (lane >> 2) + half * 8;
                float qp = 0.f;
                #pragma unroll
                for (int nf = 0; nf < 4; nf++) {
                    int lc = n_base + nf * 8 + 2 * (lane & 3);
                    qp += fmaxf(C[mf][nf][half * 2 + 0] + sb2[lc], 0.f) * sw3[lc];
                    qp += fmaxf(C[mf][nf][half * 2 + 1] + sb2[lc + 1], 0.f) * sw3[lc + 1];
                }
                qp += __shfl_xor_sync(0xffffffffu, qp, 1);
                qp += __shfl_xor_sync(0xffffffffu, qp, 2);
                if ((lane & 3) == 0 && sidx[r] == g) atomicAdd(out + b0 + r, qp);
            }
        __syncthreads();
    }
}

extern "C" void kernel_launch(void* const* d_in, const int* in_sizes, int n_in,
                              void* d_out, int out_size) {
    const float* state  = (const float*)d_in[0];
    const float* action = (const float*)d_in[1];
    const int*   idx    = (const int*)d_in[2];
    const float* W1     = (const float*)d_in[3];
    const float* b1     = (const float*)d_in[4];
    const float* W2s    = (const float*)d_in[5];
    const float* b2s    = (const float*)d_in[6];
    const float* W2a    = (const float*)d_in[7];
    const float* W3     = (const float*)d_in[8];
    const float* b3     = (const float*)d_in[9];
    float* out = (float*)d_out;

    cudaFuncSetAttribute(h1_mma_kernel,  cudaFuncAttributeMaxDynamicSharedMemorySize, SMEM_BYTES);
    cudaFuncSetAttribute(h2q_mma_kernel, cudaFuncAttributeMaxDynamicSharedMemorySize, SMEM_BYTES);

    prep_kernel<<<PREP_BLOCKS, 256>>>(state, action, idx, W1, W2s, W2a, b3, out);
    h1_mma_kernel<<<dim3(5, B_TOT / 128), 512, SMEM_BYTES>>>(idx, b1);
    h2q_mma_kernel<<<dim3(4, B_TOT / 128), 512, SMEM_BYTES>>>(idx, b2s, W3, out);
}

// round 6
// speedup vs baseline: 1.0986x; 1.0986x over previous
#include <cuda_runtime.h>
#include <cuda_bf16.h>
#include <cstdint>
#include <cstddef>

#define B_TOT 32768
#define D_IN  128
#define A_DIM 16
#define H1D   600
#define H2D   500
#define KP    640
#define G_N   8

#define CK     64
#define ROWB   144u
#define A_HALF 18432u  // 128 rows * 144B
#define B_HALF 9216u   // 64 rows * 144B
#define STAGE_BYTES (2u*A_HALF + 2u*B_HALF)  // 55296
#define SMEM_BYTES  (2*STAGE_BYTES + 1024)

// ---- persistent device scratch (pre-split bf16 hi/lo operands) ----
__device__ __nv_bfloat16 g_h1hi[(size_t)B_TOT * KP];
__device__ __nv_bfloat16 g_h1lo[(size_t)B_TOT * KP];
__device__ __nv_bfloat16 g_Sh[(size_t)B_TOT * D_IN];
__device__ __nv_bfloat16 g_Sl[(size_t)B_TOT * D_IN];
__device__ __nv_bfloat16 g_W1h[(size_t)G_N * 640 * D_IN];
__device__ __nv_bfloat16 g_W1l[(size_t)G_N * 640 * D_IN];
__device__ __nv_bfloat16 g_W2h[(size_t)512 * 576];
__device__ __nv_bfloat16 g_W2l[(size_t)512 * 576];
__device__ __nv_bfloat16 g_Bth[(size_t)G_N * 512 * 64];
__device__ __nv_bfloat16 g_Btl[(size_t)G_N * 512 * 64];

// ---------------- helpers ----------------
__device__ __forceinline__ uint32_t smem_u32(const void* p) {
    uint32_t a;
    asm("{ .reg .u64 t; cvta.to.shared.u64 t, %1; cvt.u32.u64 %0, t; }" : "=r"(a) : "l"(p));
    return a;
}
__device__ __forceinline__ void ldm_x4(uint32_t* r, uint32_t addr) {
    asm volatile("ldmatrix.sync.aligned.m8n8.x4.shared.b16 {%0,%1,%2,%3}, [%4];"
                 : "=r"(r[0]), "=r"(r[1]), "=r"(r[2]), "=r"(r[3]) : "r"(addr));
}
__device__ __forceinline__ void mma16816(float* c, const uint32_t* a, const uint32_t* b) {
    asm volatile("mma.sync.aligned.m16n8k16.row.col.f32.bf16.bf16.f32 "
                 "{%0,%1,%2,%3}, {%4,%5,%6,%7}, {%8,%9}, {%0,%1,%2,%3};"
                 : "+f"(c[0]), "+f"(c[1]), "+f"(c[2]), "+f"(c[3])
                 : "r"(a[0]), "r"(a[1]), "r"(a[2]), "r"(a[3]), "r"(b[0]), "r"(b[1]));
}
__device__ __forceinline__ void cp16(uint32_t dst, const void* src) {
    asm volatile("cp.async.cg.shared.global [%0], [%1], 16;" :: "r"(dst), "l"(src) : "memory");
}
__device__ __forceinline__ void cp_commit() { asm volatile("cp.async.commit_group;" ::: "memory"); }
__device__ __forceinline__ void cp_wait0() { asm volatile("cp.async.wait_group 0;" ::: "memory"); }

__device__ __forceinline__ uint32_t pack2(float f0, float f1) {
    uint32_t r;
    asm("cvt.rn.bf16x2.f32 %0, %1, %2;" : "=r"(r) : "f"(f1), "f"(f0));
    return r;
}
__device__ __forceinline__ void split2(float f0, float f1, uint32_t& h, uint32_t& l) {
    h = pack2(f0, f1);
    float h0 = __uint_as_float(h << 16);
    float h1 = __uint_as_float(h & 0xffff0000u);
    l = pack2(f0 - h0, f1 - h1);
}
__device__ __forceinline__ void split8(float4 v0, float4 v1, uint4& H, uint4& L) {
    split2(v0.x, v0.y, H.x, L.x);
    split2(v0.z, v0.w, H.y, L.y);
    split2(v1.x, v1.y, H.z, L.z);
    split2(v1.z, v1.w, H.w, L.w);
}

// ---------------- fused prep kernel ----------------
// block regions: [0,128) init_out | [128,256) fill_pad | [256,2304) split_state
//                [2304,2624) split_W1 | [2624,2768) split_W2 | [2768,2896) split_Bt
#define PREP_BLOCKS 2896
__global__ __launch_bounds__(256) void prep_kernel(const float* __restrict__ state,
                                                   const float* __restrict__ action,
                                                   const int* __restrict__ idx,
                                                   const float* __restrict__ W1,
                                                   const float* __restrict__ W2s,
                                                   const float* __restrict__ W2a,
                                                   const float* __restrict__ b3,
                                                   float* __restrict__ out) {
    const int blk = blockIdx.x;
    const int t = threadIdx.x;
    if (blk < 128) {
        int i = blk * 256 + t;
        out[i] = b3[idx[i]];
    } else if (blk < 256) {
        int b = (blk - 128) * 256 + t;
        const float4* a4 = (const float4*)(action + (size_t)b * A_DIM);
        uint4 H0, L0, H1, L1;
        split8(a4[0], a4[1], H0, L0);
        split8(a4[2], a4[3], H1, L1);
        uint16_t* ph = (uint16_t*)g_h1hi + (size_t)b * KP + 600;
        uint16_t* pl = (uint16_t*)g_h1lo + (size_t)b * KP + 600;
        ((uint4*)ph)[0] = H0; ((uint4*)ph)[1] = H1;
        ((uint4*)pl)[0] = L0; ((uint4*)pl)[1] = L1;
        uint4 z = make_uint4(0, 0, 0, 0);
        ((uint4*)(ph + 16))[0] = z; ((uint4*)(ph + 16))[1] = z; ((uint4*)(ph + 16))[2] = z;
        ((uint4*)(pl + 16))[0] = z; ((uint4*)(pl + 16))[1] = z; ((uint4*)(pl + 16))[2] = z;
    } else if (blk < 2304) {
        size_t e = ((size_t)(blk - 256) * 256 + t) * 8;
        const float4* s4 = (const float4*)(state + e);
        uint4 H, L;
        split8(s4[0], s4[1], H, L);
        *(uint4*)((uint16_t*)g_Sh + e) = H;
        *(uint4*)((uint16_t*)g_Sl + e) = L;
    } else if (blk < 2624) {
        size_t e = ((size_t)(blk - 2304) * 256 + t) * 8;
        int g = (int)(e / (640 * D_IN));
        int r = (int)((e / D_IN) % 640);
        int c = (int)(e % D_IN);
        uint4 H = make_uint4(0, 0, 0, 0), L = H;
        if (r < H1D) {
            const float4* s4 = (const float4*)(W1 + ((size_t)g * H1D + r) * D_IN + c);
            split8(s4[0], s4[1], H, L);
        }
        *(uint4*)((uint16_t*)g_W1h + e) = H;
        *(uint4*)((uint16_t*)g_W1l + e) = L;
    } else if (blk < 2768) {
        size_t e = ((size_t)(blk - 2624) * 256 + t) * 8;
        int n = (int)(e / 576);
        int c = (int)(e % 576);
        uint4 H = make_uint4(0, 0, 0, 0), L = H;
        if (n < H2D) {
            const float4* s4 = (const float4*)(W2s + (size_t)n * H1D + c);
            split8(s4[0], s4[1], H, L);
        }
        *(uint4*)((uint16_t*)g_W2h + e) = H;
        *(uint4*)((uint16_t*)g_W2l + e) = L;
    } else {
        size_t e = ((size_t)(blk - 2768) * 256 + t) * 8;
        int g = (int)(e / (512 * 64));
        int n = (int)((e / 64) % 512);
        int cc = (int)(e % 64);
        float v[8];
        #pragma unroll
        for (int j = 0; j < 8; j++) {
            int c = cc + j;
            float x = 0.f;
            if (n < H2D) {
                if (c < 24) x = W2s[(size_t)n * H1D + 576 + c];
                else if (c < 40) x = W2a[((size_t)g * H2D + n) * A_DIM + (c - 24)];
            }
            v[j] = x;
        }
        uint4 H, L;
        split8(make_float4(v[0], v[1], v[2], v[3]), make_float4(v[4], v[5], v[6], v[7]), H, L);
        *(uint4*)((uint16_t*)g_Bth + e) = H;
        *(uint4*)((uint16_t*)g_Btl + e) = L;
    }
}

// ---------------- mma body: stage = [Ah|Al|Bh|Bl] ----------------
#define MMA_STAGE(sbase, s)                                                        \
    {                                                                              \
        const uint32_t SA = (sbase) + (uint32_t)(s) * STAGE_BYTES;                 \
        const uint32_t SAh = SA, SAl = SA + A_HALF;                                \
        const uint32_t SBh = SA + 2u * A_HALF, SBl = SBh + B_HALF;                 \
        _Pragma("unroll")                                                          \
        for (int kk = 0; kk < 4; kk++) {                                           \
            uint32_t ah[2][4], al[2][4], bh[4][2], bl[4][2];                       \
            _Pragma("unroll")                                                      \
            for (int mf = 0; mf < 2; mf++) {                                       \
                ldm_x4(ah[mf], SAh + aoff + mf * 2304u + kk * 32u);                \
                ldm_x4(al[mf], SAl + aoff + mf * 2304u + kk * 32u);                \
            }                                                                      \
            _Pragma("unroll")                                                      \
            for (int nq = 0; nq < 2; nq++) {                                       \
                uint32_t t[4];                                                     \
                ldm_x4(t, SBh + boff + nq * 2304u + kk * 32u);                     \
                bh[nq * 2][0] = t[0]; bh[nq * 2][1] = t[2];                        \
                bh[nq * 2 + 1][0] = t[1]; bh[nq * 2 + 1][1] = t[3];                \
                ldm_x4(t, SBl + boff + nq * 2304u + kk * 32u);                     \
                bl[nq * 2][0] = t[0]; bl[nq * 2][1] = t[2];                        \
                bl[nq * 2 + 1][0] = t[1]; bl[nq * 2 + 1][1] = t[3];                \
            }                                                                      \
            _Pragma("unroll")                                                      \
            for (int mf = 0; mf < 2; mf++)                                         \
                _Pragma("unroll")                                                  \
                for (int nf = 0; nf < 4; nf++) {                                   \
                    mma16816(C[mf][nf], ah[mf], bh[nf]);                           \
                    mma16816(C[mf][nf], ah[mf], bl[nf]);                           \
                    mma16816(C[mf][nf], al[mf], bh[nf]);                           \
                }                                                                  \
        }                                                                          \
    }

// GEMM1: h1 = relu(state . W1[g]^T + b1[g]) -> g_h1 hi/lo. M=128,N=64,K=128 (2 chunks)
__global__ __launch_bounds__(256, 2) void h1_mma_kernel(const int* __restrict__ idx,
                                                        const float* __restrict__ b1) {
    extern __shared__ char dsm[];
    const uint32_t sbase = smem_u32(dsm);
    float* sb1 = (float*)(dsm + 2 * STAGE_BYTES);
    int* sidx = (int*)(sb1 + 64);
    const int tid = threadIdx.x, lane = tid & 31, wid = tid >> 5;
    const int n0 = blockIdx.x * 64, b0 = blockIdx.y * 128;
    if (tid < 128) sidx[tid] = idx[b0 + tid];
    __syncthreads();
    const int g_lo = sidx[0], g_hi = sidx[127];
    const int m_base = (wid >> 1) * 32, n_base = (wid & 1) * 32;
    const uint32_t aoff = (uint32_t)(m_base + (lane & 15)) * ROWB + (uint32_t)((lane >> 4) * 16);
    const uint32_t boff = (uint32_t)(n_base + (lane & 15)) * ROWB + (uint32_t)((lane >> 4) * 16);

    for (int g = g_lo; g <= g_hi; ++g) {
        if (tid < 64) { int n = n0 + tid; sb1[tid] = (n < H1D) ? b1[(size_t)g * H1D + n] : 0.f; }
        auto issue = [&](int kc, int s) {
            #pragma unroll
            for (int i = 0; i < 8; i++) {
                int bid = tid + i * 256;
                int arr = bid >> 10, rem = bid & 1023;
                int row = rem >> 3, q = rem & 7;
                const __nv_bfloat16* src = (arr ? g_Sl : g_Sh) + (size_t)(b0 + row) * D_IN + kc * CK + q * 8;
                cp16(sbase + (uint32_t)s * STAGE_BYTES + (uint32_t)arr * A_HALF + row * ROWB + q * 16u, src);
            }
            #pragma unroll
            for (int i = 0; i < 4; i++) {
                int bid = tid + i * 256;
                int arr = bid >> 9, rem = bid & 511;
                int row = rem >> 3, q = rem & 7;
                const __nv_bfloat16* src = (arr ? g_W1l : g_W1h) + ((size_t)g * 640 + n0 + row) * D_IN + kc * CK + q * 8;
                cp16(sbase + (uint32_t)s * STAGE_BYTES + 2u * A_HALF + (uint32_t)arr * B_HALF + row * ROWB + q * 16u, src);
            }
            cp_commit();
        };
        float C[2][4][4];
        #pragma unroll
        for (int mf = 0; mf < 2; mf++)
            #pragma unroll
            for (int nf = 0; nf < 4; nf++)
                #pragma unroll
                for (int e = 0; e < 4; e++) C[mf][nf][e] = 0.f;

        issue(0, 0);
        cp_wait0();
        __syncthreads();
        issue(1, 1);
        MMA_STAGE(sbase, 0);
        cp_wait0();
        __syncthreads();
        MMA_STAGE(sbase, 1);

        // epilogue: +b1, relu, split, store rows owned by g
        #pragma unroll
        for (int mf = 0; mf < 2; mf++)
            #pragma unroll
            for (int half = 0; half < 2; half++) {
                int r = m_base + mf * 16 + (lane >> 2) + half * 8;
                if (sidx[r] == g) {
                    size_t base = (size_t)(b0 + r) * KP;
                    #pragma unroll
                    for (int nf = 0; nf < 4; nf++) {
                        int lc = n_base + nf * 8 + 2 * (lane & 3);
                        int n = n0 + lc;
                        if (n < H1D) {
                            float v0 = fmaxf(C[mf][nf][half * 2 + 0] + sb1[lc], 0.f);
                            float v1 = fmaxf(C[mf][nf][half * 2 + 1] + sb1[lc + 1], 0.f);
                            uint32_t h, l;
                            split2(v0, v1, h, l);
                            *(uint32_t*)(g_h1hi + base + n) = h;
                            *(uint32_t*)(g_h1lo + base + n) = l;
                        }
                    }
                }
            }
        __syncthreads();
    }
}

// GEMM2 fused: q += relu([h1|act|0].[W2s|W2a[g]|0]^T + b2s) . W3[g]. M=128,N=64,K=640
__global__ __launch_bounds__(256, 2) void h2q_mma_kernel(const int* __restrict__ idx,
                                                         const float* __restrict__ b2s,
                                                         const float* __restrict__ W3,
                                                         float* __restrict__ out) {
    extern __shared__ char dsm[];
    const uint32_t sbase = smem_u32(dsm);
    float* sb2 = (float*)(dsm + 2 * STAGE_BYTES);
    float* sw3 = sb2 + 64;
    int* sidx = (int*)(sw3 + 64);
    const int tid = threadIdx.x, lane = tid & 31, wid = tid >> 5;
    const int n0 = blockIdx.x * 64, b0 = blockIdx.y * 128;
    if (tid < 128) sidx[tid] = idx[b0 + tid];
    if (tid < 64) { int n = n0 + tid; sb2[tid] = (n < H2D) ? b2s[n] : 0.f; }
    __syncthreads();
    const int g_lo = sidx[0], g_hi = sidx[127];
    const int m_base = (wid >> 1) * 32, n_base = (wid & 1) * 32;
    const uint32_t aoff = (uint32_t)(m_base + (lane & 15)) * ROWB + (uint32_t)((lane >> 4) * 16);
    const uint32_t boff = (uint32_t)(n_base + (lane & 15)) * ROWB + (uint32_t)((lane >> 4) * 16);

    for (int g = g_lo; g <= g_hi; ++g) {
        if (tid < 64) { int n = n0 + tid; sw3[tid] = (n < H2D) ? W3[(size_t)g * H2D + n] : 0.f; }
        auto issue = [&](int kc, int s) {
            #pragma unroll
            for (int i = 0; i < 8; i++) {
                int bid = tid + i * 256;
                int arr = bid >> 10, rem = bid & 1023;
                int row = rem >> 3, q = rem & 7;
                const __nv_bfloat16* src = (arr ? g_h1lo : g_h1hi) + (size_t)(b0 + row) * KP + kc * CK + q * 8;
                cp16(sbase + (uint32_t)s * STAGE_BYTES + (uint32_t)arr * A_HALF + row * ROWB + q * 16u, src);
            }
            #pragma unroll
            for (int i = 0; i < 4; i++) {
                int bid = tid + i * 256;
                int arr = bid >> 9, rem = bid & 511;
                int row = rem >> 3, q = rem & 7;
                const __nv_bfloat16* src;
                if (kc < 9)
                    src = (arr ? g_W2l : g_W2h) + (size_t)(n0 + row) * 576 + kc * CK + q * 8;
                else
                    src = (arr ? g_Btl : g_Bth) + ((size_t)g * 512 + n0 + row) * 64 + q * 8;
                cp16(sbase + (uint32_t)s * STAGE_BYTES + 2u * A_HALF + (uint32_t)arr * B_HALF + row * ROWB + q * 16u, src);
            }
            cp_commit();
        };

        float C[2][4][4];
        #pragma unroll
        for (int mf = 0; mf < 2; mf++)
            #pragma unroll
            for (int nf = 0; nf < 4; nf++)
                #pragma unroll
                for (int e = 0; e < 4; e++) C[mf][nf][e] = 0.f;

        issue(0, 0);
        for (int kc = 0; kc < 10; ++kc) {
            cp_wait0();
            __syncthreads();                 // chunk kc visible; MMA(kc-1) done by all warps
            if (kc < 9) issue(kc + 1, (kc + 1) & 1);
            MMA_STAGE(sbase, kc & 1);
        }

        // epilogue: relu(+b2s) . W3, quad-reduce, atomicAdd
        #pragma unroll
        for (int mf = 0; mf < 2; mf++)
            #pragma unroll
            for (int half = 0; half < 2; half++) {
                int r = m_base + mf * 16 + (lane >> 2) + half * 8;
                float qp = 0.f;
                #pragma unroll
                for (int nf = 0; nf < 4; nf++) {
                    int lc = n_base + nf * 8 + 2 * (lane & 3);
                    qp += fmaxf(C[mf][nf][half * 2 + 0] + sb2[lc], 0.f) * sw3[lc];
                    qp += fmaxf(C[mf][nf][half * 2 + 1] + sb2[lc + 1], 0.f) * sw3[lc + 1];
                }
                qp += __shfl_xor_sync(0xffffffffu, qp, 1);
                qp += __shfl_xor_sync(0xffffffffu, qp, 2);
                if ((lane & 3) == 0 && sidx[r] == g) atomicAdd(out + b0 + r, qp);
            }
        __syncthreads();
    }
}

extern "C" void kernel_launch(void* const* d_in, const int* in_sizes, int n_in,
                              void* d_out, int out_size) {
    const float* state  = (const float*)d_in[0];
    const float* action = (const float*)d_in[1];
    const int*   idx    = (const int*)d_in[2];
    const float* W1     = (const float*)d_in[3];
    const float* b1     = (const float*)d_in[4];
    const float* W2s    = (const float*)d_in[5];
    const float* b2s    = (const float*)d_in[6];
    const float* W2a    = (const float*)d_in[7];
    const float* W3     = (const float*)d_in[8];
    const float* b3     = (const float*)d_in[9];
    float* out = (float*)d_out;

    cudaFuncSetAttribute(h1_mma_kernel,  cudaFuncAttributeMaxDynamicSharedMemorySize, SMEM_BYTES);
    cudaFuncSetAttribute(h2q_mma_kernel, cudaFuncAttributeMaxDynamicSharedMemorySize, SMEM_BYTES);

    prep_kernel<<<PREP_BLOCKS, 256>>>(state, action, idx, W1, W2s, W2a, b3, out);
    h1_mma_kernel<<<dim3(10, B_TOT / 128), 256, SMEM_BYTES>>>(idx, b1);
    h2q_mma_kernel<<<dim3(8, B_TOT / 128), 256, SMEM_BYTES>>>(idx, b2s, W3, out);
}